// round 9
// baseline (speedup 1.0000x reference)
#include <cuda_runtime.h>
#include <stdint.h>
#include <math.h>

#define BATCH   4096
#define LEN     4096
#define NUM_SEG 4
#define SEG_LEN 1024
#define NV      3073        // LEN - SEG_LEN + 1
#define PADN    5120        // LEN + 2*512
#define NT1     320         // 5120 / 16
#define NT2     20          // 320 / 16

// tanh pattern tables (precomputed once)
__device__ float g_pat[2][SEG_LEN];

__global__ void k_init(const float* __restrict__ pi, const float* __restrict__ pq) {
    int t = blockIdx.x * blockDim.x + threadIdx.x;
    if (t < SEG_LEN) {
        g_pat[0][t] = tanhf(pi[t]);
        g_pat[1][t] = tanhf(pq[t]);
    }
}

__global__ void __launch_bounds__(512)
k_main(const float* __restrict__ x,
       const float* __restrict__ seg_scale,
       const int*   __restrict__ rand_cols,
       const int*   __restrict__ shifts_raw,
       float*       __restrict__ out) {
    __shared__ float        BUF[PADN];     // power -> inner1 -> C
    __shared__ float        sA[NT1];       // tile sums -> inner2 -> C2
    __shared__ float        sB[32];        // level-3 (20 padded to 32)
    __shared__ float        sExcl3;        // inclusive total of first 16 level-3 elems
    __shared__ unsigned int hist[NUM_SEG][256];
    __shared__ int          mlist[NUM_SEG][64];
    __shared__ int          mcnt[NUM_SEG];
    __shared__ unsigned int sel_prefix[NUM_SEG];
    __shared__ int          sel_rank[NUM_SEG];
    __shared__ int          s_start[NUM_SEG];
    __shared__ float        s_coef[NUM_SEG];
    __shared__ float        s_amp;

    const int b   = blockIdx.x;
    const int tid = threadIdx.x;
    const float* xr = x + (size_t)b * 2 * LEN;

    // ---------- phase 1: padded power ----------
    // power[j] = rn(rn(x0*x0) + rn(x1*x1)) — XLA reduce emitter: plain
    // fmul/fadd WITHOUT contract flags; NVPTX Standard fusion does not fuse.
    for (int i = tid; i < PADN; i += 512) {
        float v = 0.0f;
        if (i >= 512 && i < 512 + LEN) {
            int j = i - 512;
            float xi = xr[j];
            float xq = xr[LEN + j];
            v = __fadd_rn(__fmul_rn(xi, xi), __fmul_rn(xq, xq));
        }
        BUF[i] = v;
    }
    __syncthreads();

    // ---------- phase 2: XLA ReduceWindowRewriter blocked scan (base 16) ----------
    // Level 1: sequential inclusive scan within each 16-tile (in place).
    if (tid < NT1) {
        float acc = BUF[16 * tid];
        #pragma unroll
        for (int r = 1; r < 16; r++) {
            acc = __fadd_rn(acc, BUF[16 * tid + r]);
            BUF[16 * tid + r] = acc;
        }
        sA[tid] = acc;   // tile sum = last element of inner scan
    }
    __syncthreads();

    // Level 2: sequential scan within each 16-tile of the 320 tile sums (in place).
    if (tid < NT2) {
        float acc = sA[16 * tid];
        #pragma unroll
        for (int r = 1; r < 16; r++) {
            acc = __fadd_rn(acc, sA[16 * tid + r]);
            sA[16 * tid + r] = acc;
        }
        sB[tid] = acc;   // level-2 tile sum
    }
    if (tid >= NT2 && tid < 32) sB[tid] = 0.0f;  // pad 20 -> 32 with identity
    __syncthreads();

    // Level 3: 20 (padded 32) elements -> [2,16] inner sequential scans, then
    // outer naive scan of the 2 block totals (exclusive = {0, total0}).
    if (tid < 2) {
        float acc = sB[16 * tid];
        #pragma unroll
        for (int r = 1; r < 16; r++) {
            acc = __fadd_rn(acc, sB[16 * tid + r]);
            sB[16 * tid + r] = acc;
        }
        if (tid == 0) sExcl3 = acc;   // inclusive total of first level-3 block
    }
    __syncthreads();

    // Combine level 3 into level 2 (C2), then level 2 into level 1 (C).
    if (tid < NT1) {
        int q = tid >> 4;        // level-2 tile of this level-1 tile
        float excl2;
        if (q == 0) excl2 = 0.0f;
        else {
            int j = q - 1;       // index into result3 (0..18)
            float e3 = (j < 16) ? 0.0f : sExcl3;
            excl2 = __fadd_rn(sB[j], e3);   // result3[j]
        }
        sA[tid] = __fadd_rn(sA[tid], excl2);   // sA now holds C2[t]
    }
    __syncthreads();

    // C[i] = inner1[i] + excl1[t],  excl1[t] = C2[t-1] (0 for t=0; +0 exact)
    for (int i = tid; i < PADN; i += 512) {
        int t = i >> 4;
        float excl1 = (t == 0) ? 0.0f : sA[t - 1];
        BUF[i] = __fadd_rn(BUF[i], excl1);
    }
    __syncthreads();
    const float* C = BUF;   // inclusive scan of padded power (rewriter rounding)

    // ---------- phase 3: amp + selection init ----------
    if (tid == 0) {
        float mean = __fadd_rn(__fdiv_rn(C[512 + LEN - 1], 8192.0f), 1e-12f);
        s_amp = 0.08f * sqrtf(mean);
    }
    if (tid < NUM_SEG) {
        sel_prefix[tid] = 0u;
        sel_rank[tid]   = rand_cols[b * NUM_SEG + tid];
        mcnt[tid]       = 0;
    }
    __syncthreads();

    // ---------- phase 4: 4-way parallel radix select over valid[l] ----------
    const int  g    = tid >> 7;     // segment/group 0..3
    const int  lt   = tid & 127;
    const bool desc = ((g & 1) == 0);   // even segs draw from high pool (descending)
    const float inv = 0.0009765625f;    // 1/1024, exact

    for (int d = 3; d >= 0; d--) {
        for (int i = lt; i < 256; i += 128) hist[g][i] = 0u;
        __syncthreads();
        const unsigned int pre = sel_prefix[g];
        const unsigned int maskAbove = (d == 3) ? 0u : (0xFFFFFFFFu << ((d + 1) * 8));
        for (int l = lt; l < NV; l += 128) {
            float c1 = C[l + 1023];
            float c0 = (l > 0) ? C[l - 1] : 0.0f;
            unsigned int u = __float_as_uint(__fmul_rn(__fsub_rn(c1, c0), inv));
            if ((u & maskAbove) == pre)
                atomicAdd(&hist[g][(u >> (d * 8)) & 255u], 1u);
        }
        __syncthreads();
        if (lt == 0) {
            int r = sel_rank[g];
            unsigned int cum = 0;
            int chosen = 0;
            if (desc) {
                for (int bin = 255; bin >= 0; bin--) {
                    cum += hist[g][bin];
                    if ((int)cum > r) { chosen = bin; r -= (int)(cum - hist[g][bin]); break; }
                }
            } else {
                for (int bin = 0; bin < 256; bin++) {
                    cum += hist[g][bin];
                    if ((int)cum > r) { chosen = bin; r -= (int)(cum - hist[g][bin]); break; }
                }
            }
            sel_prefix[g] = pre | ((unsigned int)chosen << (d * 8));
            sel_rank[g]   = r;
        }
        __syncthreads();
    }

    // final pass: r-th SMALLEST index among exact-bit duplicates (stable sort ties)
    {
        const unsigned int v = sel_prefix[g];
        for (int l = lt; l < NV; l += 128) {
            float c1 = C[l + 1023];
            float c0 = (l > 0) ? C[l - 1] : 0.0f;
            unsigned int u = __float_as_uint(__fmul_rn(__fsub_rn(c1, c0), inv));
            if (u == v) {
                int p = atomicAdd(&mcnt[g], 1);
                if (p < 64) mlist[g][p] = l;
            }
        }
        __syncthreads();
        if (lt == 0) {
            int n = min(mcnt[g], 64);
            int r = min(sel_rank[g], n - 1);
            int cur = -1;
            for (int it = 0; it <= r; it++) {
                int mn = 0x7FFFFFFF;
                for (int j = 0; j < n; j++) {
                    int val = mlist[g][j];
                    if (val > cur && val < mn) mn = val;
                }
                cur = mn;
            }
            const int idx = cur;

            // starts: strict fp32 replication of reference op sequence
            const float a0f = 409.600006103515625f;   // fp32(0.1*4096)
            const float a3f = 3194.8798828125f;       // fp32(0.78*4096)
            float step   = __fdiv_rn(__fsub_rn(a3f, a0f), 3.0f);
            float anchor = __fadd_rn(a0f, __fmul_rn((float)g, step));
            float st = __fadd_rn(__fmul_rn(0.8f, anchor), __fmul_rn(0.2f, (float)idx));
            st = __fadd_rn(st, __fsub_rn((float)shifts_raw[b * NUM_SEG + g], 16.0f));
            float rr = rintf(st);                     // round-half-even == jnp.round
            rr = fminf(fmaxf(rr, 0.0f), 3072.0f);
            s_start[g] = (int)rr;
            s_coef[g]  = __fmul_rn(s_amp, fmaxf(seg_scale[g], 0.0f));
        }
    }
    __syncthreads();

    // ---------- phase 5: apply ----------
    float* orow = out + (size_t)b * 2 * LEN;
    const int   st0 = s_start[0], st1 = s_start[1], st2 = s_start[2], st3 = s_start[3];
    const float cf0 = s_coef[0],  cf1 = s_coef[1],  cf2 = s_coef[2],  cf3 = s_coef[3];

    for (int l = tid; l < LEN; l += 512) {
        float a0 = 0.0f, a1 = 0.0f;
        int off;
        off = l - st0; if ((unsigned)off < (unsigned)SEG_LEN) { a0 += cf0 * g_pat[0][off]; a1 += cf0 * g_pat[1][off]; }
        off = l - st1; if ((unsigned)off < (unsigned)SEG_LEN) { a0 += cf1 * g_pat[0][off]; a1 += cf1 * g_pat[1][off]; }
        off = l - st2; if ((unsigned)off < (unsigned)SEG_LEN) { a0 += cf2 * g_pat[0][off]; a1 += cf2 * g_pat[1][off]; }
        off = l - st3; if ((unsigned)off < (unsigned)SEG_LEN) { a0 += cf3 * g_pat[0][off]; a1 += cf3 * g_pat[1][off]; }
        orow[l]       = xr[l]       + a0;
        orow[LEN + l] = xr[LEN + l] + a1;
    }
}

extern "C" void kernel_launch(void* const* d_in, const int* in_sizes, int n_in,
                              void* d_out, int out_size) {
    const float* x          = (const float*)d_in[0];
    const float* pattern_i  = (const float*)d_in[1];
    const float* pattern_q  = (const float*)d_in[2];
    const float* seg_scale  = (const float*)d_in[3];
    const int*   rand_cols  = (const int*)d_in[4];
    const int*   shifts_raw = (const int*)d_in[5];
    float*       out        = (float*)d_out;

    k_init<<<4, 512>>>(pattern_i, pattern_q);
    k_main<<<BATCH, 512>>>(x, seg_scale, rand_cols, shifts_raw, out);
}

// round 10
// speedup vs baseline: 1.0535x; 1.0535x over previous
#include <cuda_runtime.h>
#include <stdint.h>
#include <math.h>

#define BATCH   4096
#define LEN     4096
#define NUM_SEG 4
#define SEG_LEN 1024
#define NV      3073        // LEN - SEG_LEN + 1
#define PADN    5120        // LEN + 2*512
#define NT1     320         // 5120 / 16
#define NT2     20          // 320 / 16
#define MCAP    48

// tanh pattern tables (precomputed once)
__device__ float g_pat[2][SEG_LEN];

__global__ void k_init(const float* __restrict__ pi, const float* __restrict__ pq) {
    int t = blockIdx.x * blockDim.x + threadIdx.x;
    if (t < SEG_LEN) {
        g_pat[0][t] = tanhf(pi[t]);
        g_pat[1][t] = tanhf(pq[t]);
    }
}

// warp-aggregated histogram increment: one atomic per distinct bin per warp
__device__ __forceinline__ void hist_add(unsigned int* h, unsigned int bin, bool cond) {
    unsigned int active = __ballot_sync(0xFFFFFFFFu, cond);
    if (cond) {
        unsigned int mm = __match_any_sync(active, bin);
        unsigned int leader = __ffs(mm) - 1u;
        if ((threadIdx.x & 31u) == leader)
            atomicAdd(&h[bin], (unsigned int)__popc(mm));
    }
}

__global__ void __launch_bounds__(512)
k_main(const float* __restrict__ x,
       const float* __restrict__ seg_scale,
       const int*   __restrict__ rand_cols,
       const int*   __restrict__ shifts_raw,
       float*       __restrict__ out) {
    __shared__ float        BUF[PADN];       // power -> inner1 -> C
    __shared__ unsigned int US[NV];          // valid[l] bit patterns
    __shared__ float        sA[NT1];
    __shared__ float        sB[32];
    __shared__ float        sExcl3;
    __shared__ unsigned int hist[NUM_SEG][256];
    __shared__ int          mlist[NUM_SEG][MCAP];
    __shared__ int          mcnt[NUM_SEG];
    __shared__ unsigned int sel_prefix[NUM_SEG];
    __shared__ int          sel_rank[NUM_SEG];
    __shared__ int          s_start[NUM_SEG];
    __shared__ float        s_coef[NUM_SEG];
    __shared__ float        s_amp;

    const int b   = blockIdx.x;
    const int tid = threadIdx.x;
    const float* xr = x + (size_t)b * 2 * LEN;

    // ---------- phase 1: padded power (float4, identical arithmetic) ----------
    // power[j] = rn(rn(x0*x0) + rn(x1*x1))
    {
        const float4* x4 = (const float4*)xr;
        #pragma unroll
        for (int v = tid; v < 1024; v += 512) {
            float4 a = x4[v];
            float4 c = x4[1024 + v];
            int o = 512 + 4 * v;
            BUF[o + 0] = __fadd_rn(__fmul_rn(a.x, a.x), __fmul_rn(c.x, c.x));
            BUF[o + 1] = __fadd_rn(__fmul_rn(a.y, a.y), __fmul_rn(c.y, c.y));
            BUF[o + 2] = __fadd_rn(__fmul_rn(a.z, a.z), __fmul_rn(c.z, c.z));
            BUF[o + 3] = __fadd_rn(__fmul_rn(a.w, a.w), __fmul_rn(c.w, c.w));
        }
        BUF[tid] = 0.0f;            // pad [0,512)
        BUF[4608 + tid % 512] = 0.0f;  // pad [4608,5120)
    }
    __syncthreads();

    // ---------- phase 2: XLA ReduceWindowRewriter blocked scan (base 16) ----------
    if (tid < NT1) {
        float acc = BUF[16 * tid];
        #pragma unroll
        for (int r = 1; r < 16; r++) {
            acc = __fadd_rn(acc, BUF[16 * tid + r]);
            BUF[16 * tid + r] = acc;
        }
        sA[tid] = acc;
    }
    __syncthreads();

    if (tid < NT2) {
        float acc = sA[16 * tid];
        #pragma unroll
        for (int r = 1; r < 16; r++) {
            acc = __fadd_rn(acc, sA[16 * tid + r]);
            sA[16 * tid + r] = acc;
        }
        sB[tid] = acc;
    }
    if (tid >= NT2 && tid < 32) sB[tid] = 0.0f;
    __syncthreads();

    if (tid < 2) {
        float acc = sB[16 * tid];
        #pragma unroll
        for (int r = 1; r < 16; r++) {
            acc = __fadd_rn(acc, sB[16 * tid + r]);
            sB[16 * tid + r] = acc;
        }
        if (tid == 0) sExcl3 = acc;
    }
    __syncthreads();

    if (tid < NT1) {
        int q = tid >> 4;
        float excl2;
        if (q == 0) excl2 = 0.0f;
        else {
            int j = q - 1;
            float e3 = (j < 16) ? 0.0f : sExcl3;
            excl2 = __fadd_rn(sB[j], e3);
        }
        sA[tid] = __fadd_rn(sA[tid], excl2);
    }
    __syncthreads();

    for (int i = tid; i < PADN; i += 512) {
        int t = i >> 4;
        float excl1 = (t == 0) ? 0.0f : sA[t - 1];
        BUF[i] = __fadd_rn(BUF[i], excl1);
    }
    __syncthreads();
    const float* C = BUF;

    // ---------- phase 3: u[l] precompute + amp + init ----------
    {
        const float inv = 0.0009765625f;   // 1/1024, exact
        for (int base = 0; base < NV; base += 512) {
            int l = base + tid;
            if (l < NV) {
                float c1 = C[l + 1023];
                float c0 = (l > 0) ? C[l - 1] : 0.0f;
                US[l] = __float_as_uint(__fmul_rn(__fsub_rn(c1, c0), inv));
            }
        }
    }
    if (tid == 0) {
        float mean = __fadd_rn(__fdiv_rn(C[512 + LEN - 1], 8192.0f), 1e-12f);
        s_amp = 0.08f * sqrtf(mean);
    }
    if (tid < NUM_SEG) {
        sel_rank[tid] = rand_cols[b * NUM_SEG + tid];
        mcnt[tid]     = 0;
    }
    // zero all histograms (1024 words)
    ((unsigned int*)hist)[tid] = 0u;
    ((unsigned int*)hist)[512 + tid] = 0u;
    __syncthreads();

    const int  g    = tid >> 7;       // group 0..3
    const int  lt   = tid & 127;
    const bool desc = ((g & 1) == 0); // even segs: high pool (descending)

    // ---------- pass A (shared): histogram of top byte, all 512 threads ----------
    {
        unsigned int* hs = hist[0];
        for (int base = 0; base < NV; base += 512) {
            int l = base + tid;
            bool inb = l < NV;
            unsigned int bin = inb ? (US[l] >> 24) : 0u;
            hist_add(hs, bin, inb);
        }
        __syncthreads();
        if (lt == 0) {
            int r = sel_rank[g];
            unsigned int cum = 0; int chosen = 0;
            if (desc) { for (int bin = 255; bin >= 0; bin--) { cum += hist[0][bin]; if ((int)cum > r) { chosen = bin; r -= (int)(cum - hist[0][bin]); break; } } }
            else      { for (int bin = 0; bin < 256; bin++)  { cum += hist[0][bin]; if ((int)cum > r) { chosen = bin; r -= (int)(cum - hist[0][bin]); break; } } }
            sel_prefix[g] = (unsigned int)chosen << 24;
            sel_rank[g]   = r;
        }
        __syncthreads();
        // re-zero histograms for per-group passes
        ((unsigned int*)hist)[tid] = 0u;
        ((unsigned int*)hist)[512 + tid] = 0u;
        __syncthreads();
    }

    // ---------- pass B (per group): byte 2 ----------
    {
        const unsigned int pre = sel_prefix[g];
        for (int base = 0; base < NV; base += 128) {
            int l = base + lt;
            bool inb = l < NV;
            unsigned int u = inb ? US[l] : 0u;
            bool cond = inb && ((u & 0xFF000000u) == pre);
            hist_add(hist[g], (u >> 16) & 255u, cond);
        }
        __syncthreads();
        if (lt == 0) {
            int r = sel_rank[g];
            unsigned int cum = 0; int chosen = 0;
            if (desc) { for (int bin = 255; bin >= 0; bin--) { cum += hist[g][bin]; if ((int)cum > r) { chosen = bin; r -= (int)(cum - hist[g][bin]); break; } } }
            else      { for (int bin = 0; bin < 256; bin++)  { cum += hist[g][bin]; if ((int)cum > r) { chosen = bin; r -= (int)(cum - hist[g][bin]); break; } } }
            sel_prefix[g] = pre | ((unsigned int)chosen << 16);
            sel_rank[g]   = r;
        }
        __syncthreads();
        ((unsigned int*)hist)[tid] = 0u;
        ((unsigned int*)hist)[512 + tid] = 0u;
        __syncthreads();
    }

    // ---------- pass C (per group): byte 1 ----------
    {
        const unsigned int pre = sel_prefix[g];
        for (int base = 0; base < NV; base += 128) {
            int l = base + lt;
            bool inb = l < NV;
            unsigned int u = inb ? US[l] : 0u;
            bool cond = inb && ((u & 0xFFFF0000u) == pre);
            hist_add(hist[g], (u >> 8) & 255u, cond);
        }
        __syncthreads();
        if (lt == 0) {
            int r = sel_rank[g];
            unsigned int cum = 0; int chosen = 0;
            if (desc) { for (int bin = 255; bin >= 0; bin--) { cum += hist[g][bin]; if ((int)cum > r) { chosen = bin; r -= (int)(cum - hist[g][bin]); break; } } }
            else      { for (int bin = 0; bin < 256; bin++)  { cum += hist[g][bin]; if ((int)cum > r) { chosen = bin; r -= (int)(cum - hist[g][bin]); break; } } }
            sel_prefix[g] = pre | ((unsigned int)chosen << 8);
            sel_rank[g]   = r;
        }
        __syncthreads();
    }

    // ---------- compact: all values matching the 24-bit prefix ----------
    {
        const unsigned int pre24 = sel_prefix[g];
        for (int base = 0; base < NV; base += 128) {
            int l = base + lt;
            if (l < NV && ((US[l] & 0xFFFFFF00u) == pre24)) {
                int p = atomicAdd(&mcnt[g], 1);
                if (p < MCAP) mlist[g][p] = l;
            }
        }
        __syncthreads();
        if (lt == 0) {
            int n = min(mcnt[g], MCAP);
            int r = min(sel_rank[g], n - 1);
            // r-th smallest 64-bit key; asc: (u, l), desc: (~u, l) — index-ascending ties
            unsigned long long cur = 0ULL;
            int idx = 0;
            for (int it = 0; it <= r; it++) {
                unsigned long long mn = 0xFFFFFFFFFFFFFFFFULL;
                int mnidx = 0;
                for (int j = 0; j < n; j++) {
                    int l = mlist[g][j];
                    unsigned int uv = US[l];
                    unsigned int key_hi = desc ? ~uv : uv;
                    unsigned long long key = ((unsigned long long)key_hi << 32) | (unsigned int)l;
                    if (key > cur && key < mn) { mn = key; mnidx = l; }
                }
                cur = mn;
                idx = mnidx;
            }

            // starts: strict fp32 replication of reference op sequence
            const float a0f = 409.600006103515625f;   // fp32(0.1*4096)
            const float a3f = 3194.8798828125f;       // fp32(0.78*4096)
            float step   = __fdiv_rn(__fsub_rn(a3f, a0f), 3.0f);
            float anchor = __fadd_rn(a0f, __fmul_rn((float)g, step));
            float st = __fadd_rn(__fmul_rn(0.8f, anchor), __fmul_rn(0.2f, (float)idx));
            st = __fadd_rn(st, __fsub_rn((float)shifts_raw[b * NUM_SEG + g], 16.0f));
            float rr = rintf(st);
            rr = fminf(fmaxf(rr, 0.0f), 3072.0f);
            s_start[g] = (int)rr;
            s_coef[g]  = __fmul_rn(s_amp, fmaxf(seg_scale[g], 0.0f));
        }
    }
    __syncthreads();

    // ---------- apply (float4) ----------
    {
        const float4* x4 = (const float4*)xr;
        float4* o4 = (float4*)(out + (size_t)b * 2 * LEN);
        const int   st0 = s_start[0], st1 = s_start[1], st2 = s_start[2], st3 = s_start[3];
        const float cf0 = s_coef[0],  cf1 = s_coef[1],  cf2 = s_coef[2],  cf3 = s_coef[3];

        #pragma unroll
        for (int v = tid; v < 1024; v += 512) {
            int l = 4 * v;
            float4 xa = x4[v];
            float4 xb = x4[1024 + v];
            float a[4] = {0.f, 0.f, 0.f, 0.f};
            float c[4] = {0.f, 0.f, 0.f, 0.f};
            #pragma unroll
            for (int j = 0; j < 4; j++) {
                int o;
                o = l + j - st0; if ((unsigned)o < (unsigned)SEG_LEN) { a[j] += cf0 * g_pat[0][o]; c[j] += cf0 * g_pat[1][o]; }
                o = l + j - st1; if ((unsigned)o < (unsigned)SEG_LEN) { a[j] += cf1 * g_pat[0][o]; c[j] += cf1 * g_pat[1][o]; }
                o = l + j - st2; if ((unsigned)o < (unsigned)SEG_LEN) { a[j] += cf2 * g_pat[0][o]; c[j] += cf2 * g_pat[1][o]; }
                o = l + j - st3; if ((unsigned)o < (unsigned)SEG_LEN) { a[j] += cf3 * g_pat[0][o]; c[j] += cf3 * g_pat[1][o]; }
            }
            float4 oa, ob;
            oa.x = xa.x + a[0]; oa.y = xa.y + a[1]; oa.z = xa.z + a[2]; oa.w = xa.w + a[3];
            ob.x = xb.x + c[0]; ob.y = xb.y + c[1]; ob.z = xb.z + c[2]; ob.w = xb.w + c[3];
            o4[v] = oa;
            o4[1024 + v] = ob;
        }
    }
}

extern "C" void kernel_launch(void* const* d_in, const int* in_sizes, int n_in,
                              void* d_out, int out_size) {
    const float* x          = (const float*)d_in[0];
    const float* pattern_i  = (const float*)d_in[1];
    const float* pattern_q  = (const float*)d_in[2];
    const float* seg_scale  = (const float*)d_in[3];
    const int*   rand_cols  = (const int*)d_in[4];
    const int*   shifts_raw = (const int*)d_in[5];
    float*       out        = (float*)d_out;

    k_init<<<4, 512>>>(pattern_i, pattern_q);
    k_main<<<BATCH, 512>>>(x, seg_scale, rand_cols, shifts_raw, out);
}

// round 11
// speedup vs baseline: 1.4219x; 1.3496x over previous
#include <cuda_runtime.h>
#include <stdint.h>
#include <math.h>

#define BATCH   4096
#define LEN     4096
#define NUM_SEG 4
#define SEG_LEN 1024
#define NV      3073        // LEN - SEG_LEN + 1
#define PADN    5120        // LEN + 2*512
#define NT1     320         // 5120 / 16
#define NT2     20          // 320 / 16
#define MCAP    48

// tanh pattern tables (precomputed once)
__device__ float g_pat[2][SEG_LEN];

__global__ void k_init(const float* __restrict__ pi, const float* __restrict__ pq) {
    int t = blockIdx.x * blockDim.x + threadIdx.x;
    if (t < SEG_LEN) {
        g_pat[0][t] = tanhf(pi[t]);
        g_pat[1][t] = tanhf(pq[t]);
    }
}

// warp-aggregated histogram increment: one atomic per distinct bin per warp
__device__ __forceinline__ void hist_add(unsigned int* h, unsigned int bin, bool cond) {
    unsigned int active = __ballot_sync(0xFFFFFFFFu, cond);
    if (cond) {
        unsigned int mm = __match_any_sync(active, bin);
        unsigned int leader = __ffs(mm) - 1u;
        if ((threadIdx.x & 31u) == leader)
            atomicAdd(&h[bin], (unsigned int)__popc(mm));
    }
}

// valid[l] bit pattern (all valid > 0, so uint order == float order)
__device__ __forceinline__ unsigned int u_of(const float* C, int l) {
    float c1 = C[l + 1023];
    float c0 = (l > 0) ? C[l - 1] : 0.0f;
    return __float_as_uint(__fmul_rn(__fsub_rn(c1, c0), 0.0009765625f));
}

// leader-side: pick bin containing rank r, update prefix/rank
__device__ __forceinline__ void decide(const unsigned int* h, bool desc, int shift,
                                       unsigned int* prefix, int* rank) {
    int r = *rank;
    unsigned int cum = 0; int chosen = 0;
    if (desc) {
        for (int bin = 255; bin >= 0; bin--) {
            cum += h[bin];
            if ((int)cum > r) { chosen = bin; r -= (int)(cum - h[bin]); break; }
        }
    } else {
        for (int bin = 0; bin < 256; bin++) {
            cum += h[bin];
            if ((int)cum > r) { chosen = bin; r -= (int)(cum - h[bin]); break; }
        }
    }
    *prefix |= (unsigned int)chosen << shift;
    *rank = r;
}

__global__ void __launch_bounds__(512)
k_main(const float* __restrict__ x,
       const float* __restrict__ seg_scale,
       const int*   __restrict__ rand_cols,
       const int*   __restrict__ shifts_raw,
       float*       __restrict__ out) {
    __shared__ __align__(16) float BUF[PADN];   // power -> inner1 -> C
    __shared__ float        sA[NT1];
    __shared__ float        sB[32];
    __shared__ float        sExcl3;
    __shared__ unsigned int histA[NUM_SEG][256];
    __shared__ unsigned int histB[NUM_SEG][256];
    __shared__ int          mlist[NUM_SEG][MCAP];
    __shared__ int          mcnt[NUM_SEG];
    __shared__ unsigned int sel_prefix[NUM_SEG];
    __shared__ int          sel_rank[NUM_SEG];
    __shared__ int          s_start[NUM_SEG];
    __shared__ float        s_coef[NUM_SEG];
    __shared__ float        s_amp;

    const int b   = blockIdx.x;
    const int tid = threadIdx.x;
    const float* xr = x + (size_t)b * 2 * LEN;

    // ---------- phase 1: padded power (float4) + init ----------
    // power[j] = rn(rn(x0*x0) + rn(x1*x1)) — XLA reduce emitter, no contraction
    {
        const float4* x4 = (const float4*)xr;
        #pragma unroll
        for (int v = tid; v < 1024; v += 512) {
            float4 a = x4[v];
            float4 c = x4[1024 + v];
            int o = 512 + 4 * v;
            BUF[o + 0] = __fadd_rn(__fmul_rn(a.x, a.x), __fmul_rn(c.x, c.x));
            BUF[o + 1] = __fadd_rn(__fmul_rn(a.y, a.y), __fmul_rn(c.y, c.y));
            BUF[o + 2] = __fadd_rn(__fmul_rn(a.z, a.z), __fmul_rn(c.z, c.z));
            BUF[o + 3] = __fadd_rn(__fmul_rn(a.w, a.w), __fmul_rn(c.w, c.w));
        }
        BUF[tid] = 0.0f;           // pad [0,512)
        BUF[4608 + tid] = 0.0f;    // pad [4608,5120)
        // init hists & selection state
        ((unsigned int*)histA)[tid] = 0u; ((unsigned int*)histA)[512 + tid] = 0u;
        ((unsigned int*)histB)[tid] = 0u; ((unsigned int*)histB)[512 + tid] = 0u;
        if (tid < NUM_SEG) {
            sel_rank[tid]   = rand_cols[b * NUM_SEG + tid];
            sel_prefix[tid] = 0u;
            mcnt[tid]       = 0;
        }
    }
    __syncthreads();

    // ---------- phase 2: XLA ReduceWindowRewriter blocked scan (base 16) ----------
    // Level 1: sequential inclusive scan within each 16-tile (vectorized LDS/STS,
    // identical left-fold rounding).
    if (tid < NT1) {
        float4* t4 = (float4*)(BUF + 16 * tid);
        float4 v0 = t4[0], v1 = t4[1], v2 = t4[2], v3 = t4[3];
        float s;
        s = v0.x;
        s = __fadd_rn(s, v0.y); v0.y = s;
        s = __fadd_rn(s, v0.z); v0.z = s;
        s = __fadd_rn(s, v0.w); v0.w = s;
        s = __fadd_rn(s, v1.x); v1.x = s;
        s = __fadd_rn(s, v1.y); v1.y = s;
        s = __fadd_rn(s, v1.z); v1.z = s;
        s = __fadd_rn(s, v1.w); v1.w = s;
        s = __fadd_rn(s, v2.x); v2.x = s;
        s = __fadd_rn(s, v2.y); v2.y = s;
        s = __fadd_rn(s, v2.z); v2.z = s;
        s = __fadd_rn(s, v2.w); v2.w = s;
        s = __fadd_rn(s, v3.x); v3.x = s;
        s = __fadd_rn(s, v3.y); v3.y = s;
        s = __fadd_rn(s, v3.z); v3.z = s;
        s = __fadd_rn(s, v3.w); v3.w = s;
        t4[0] = v0; t4[1] = v1; t4[2] = v2; t4[3] = v3;
        sA[tid] = s;
    }
    __syncthreads();

    // Level 2: sequential scan within each 16-tile of the 320 tile sums.
    if (tid < NT2) {
        float acc = sA[16 * tid];
        #pragma unroll
        for (int r = 1; r < 16; r++) {
            acc = __fadd_rn(acc, sA[16 * tid + r]);
            sA[16 * tid + r] = acc;
        }
        sB[tid] = acc;
    }
    if (tid >= NT2 && tid < 32) sB[tid] = 0.0f;
    __syncthreads();

    // Level 3: [2,16] inner sequential scans over the padded 32.
    if (tid < 2) {
        float acc = sB[16 * tid];
        #pragma unroll
        for (int r = 1; r < 16; r++) {
            acc = __fadd_rn(acc, sB[16 * tid + r]);
            sB[16 * tid + r] = acc;
        }
        if (tid == 0) sExcl3 = acc;
    }
    __syncthreads();

    // Combine level 3 into level 2 (C2 in sA).
    if (tid < NT1) {
        int q = tid >> 4;
        float excl2;
        if (q == 0) excl2 = 0.0f;
        else {
            int j = q - 1;
            float e3 = (j < 16) ? 0.0f : sExcl3;
            excl2 = __fadd_rn(sB[j], e3);
        }
        sA[tid] = __fadd_rn(sA[tid], excl2);
    }
    __syncthreads();

    // C[i] = inner1[i] + C2[t-1] (vectorized per 16-tile; identical rounding)
    if (tid < NT1) {
        float excl1 = (tid == 0) ? 0.0f : sA[tid - 1];
        float4* t4 = (float4*)(BUF + 16 * tid);
        #pragma unroll
        for (int q = 0; q < 4; q++) {
            float4 v = t4[q];
            v.x = __fadd_rn(v.x, excl1);
            v.y = __fadd_rn(v.y, excl1);
            v.z = __fadd_rn(v.z, excl1);
            v.w = __fadd_rn(v.w, excl1);
            t4[q] = v;
        }
    }
    __syncthreads();
    const float* C = BUF;

    // ---------- selection: fused radix passes (all 512 threads serve 4 groups) ----------
    const int g  = tid >> 7;          // this thread's group for decide/final steps
    const int lt = tid & 127;

    // amp (any order; tolerance ample)
    if (tid == 256) {
        float mean = __fadd_rn(__fdiv_rn(C[512 + LEN - 1], 8192.0f), 1e-12f);
        s_amp = 0.08f * sqrtf(mean);
    }

    // pass A: top byte, single shared histogram histA[0]
    for (int base = 0; base < NV; base += 512) {
        int l = base + tid;
        bool inb = l < NV;
        unsigned int u = inb ? u_of(C, l) : 0u;
        hist_add(histA[0], u >> 24, inb);
    }
    __syncthreads();
    if (lt == 0) {
        unsigned int p = 0u; int r = sel_rank[g];
        decide(histA[0], (g & 1) == 0, 24, &p, &r);
        sel_prefix[g] = p; sel_rank[g] = r;
    }
    __syncthreads();

    // pass B: byte 2, fused over groups (histB); also re-zero histA[0]
    {
        unsigned int p0 = sel_prefix[0], p1 = sel_prefix[1],
                     p2 = sel_prefix[2], p3 = sel_prefix[3];
        if (tid < 256) histA[0][tid] = 0u;
        for (int base = 0; base < NV; base += 512) {
            int l = base + tid;
            bool inb = l < NV;
            unsigned int u = inb ? u_of(C, l) : 0u;
            unsigned int hi = u & 0xFF000000u;
            unsigned int bin = (u >> 16) & 255u;
            hist_add(histB[0], bin, inb && hi == p0);
            hist_add(histB[1], bin, inb && hi == p1);
            hist_add(histB[2], bin, inb && hi == p2);
            hist_add(histB[3], bin, inb && hi == p3);
        }
    }
    __syncthreads();
    if (lt == 0) {
        unsigned int p = sel_prefix[g]; int r = sel_rank[g];
        decide(histB[g], (g & 1) == 0, 16, &p, &r);
        sel_prefix[g] = p; sel_rank[g] = r;
    }
    __syncthreads();

    // pass C: byte 1, fused over groups (histA: [0] re-zeroed, [1..3] untouched-zero)
    {
        unsigned int p0 = sel_prefix[0], p1 = sel_prefix[1],
                     p2 = sel_prefix[2], p3 = sel_prefix[3];
        for (int base = 0; base < NV; base += 512) {
            int l = base + tid;
            bool inb = l < NV;
            unsigned int u = inb ? u_of(C, l) : 0u;
            unsigned int hi = u & 0xFFFF0000u;
            unsigned int bin = (u >> 8) & 255u;
            hist_add(histA[0], bin, inb && hi == p0);
            hist_add(histA[1], bin, inb && hi == p1);
            hist_add(histA[2], bin, inb && hi == p2);
            hist_add(histA[3], bin, inb && hi == p3);
        }
    }
    __syncthreads();
    if (lt == 0) {
        unsigned int p = sel_prefix[g]; int r = sel_rank[g];
        decide(histA[g], (g & 1) == 0, 8, &p, &r);
        sel_prefix[g] = p; sel_rank[g] = r;
    }
    __syncthreads();

    // compact: values matching each group's 24-bit prefix (fused)
    {
        unsigned int p0 = sel_prefix[0], p1 = sel_prefix[1],
                     p2 = sel_prefix[2], p3 = sel_prefix[3];
        for (int base = 0; base < NV; base += 512) {
            int l = base + tid;
            if (l >= NV) continue;
            unsigned int hi = u_of(C, l) & 0xFFFFFF00u;
            if (hi == p0) { int p = atomicAdd(&mcnt[0], 1); if (p < MCAP) mlist[0][p] = l; }
            if (hi == p1) { int p = atomicAdd(&mcnt[1], 1); if (p < MCAP) mlist[1][p] = l; }
            if (hi == p2) { int p = atomicAdd(&mcnt[2], 1); if (p < MCAP) mlist[2][p] = l; }
            if (hi == p3) { int p = atomicAdd(&mcnt[3], 1); if (p < MCAP) mlist[3][p] = l; }
        }
    }
    __syncthreads();

    // final decide per group: r-th smallest 64-bit key (value, index); desc flips value
    if (lt == 0) {
        const bool desc = (g & 1) == 0;
        int n = min(mcnt[g], MCAP);
        int r = min(sel_rank[g], n - 1);
        unsigned long long cur = 0ULL;
        int idx = 0;
        for (int it = 0; it <= r; it++) {
            unsigned long long mn = 0xFFFFFFFFFFFFFFFFULL;
            int mnidx = 0;
            for (int j = 0; j < n; j++) {
                int l = mlist[g][j];
                unsigned int uv = u_of(C, l);
                unsigned int key_hi = desc ? ~uv : uv;
                unsigned long long key = ((unsigned long long)key_hi << 32) | (unsigned int)l;
                if (key > cur && key < mn) { mn = key; mnidx = l; }
            }
            cur = mn;
            idx = mnidx;
        }

        // starts: strict fp32 replication of reference op sequence
        const float a0f = 409.600006103515625f;   // fp32(0.1*4096)
        const float a3f = 3194.8798828125f;       // fp32(0.78*4096)
        float step   = __fdiv_rn(__fsub_rn(a3f, a0f), 3.0f);
        float anchor = __fadd_rn(a0f, __fmul_rn((float)g, step));
        float st = __fadd_rn(__fmul_rn(0.8f, anchor), __fmul_rn(0.2f, (float)idx));
        st = __fadd_rn(st, __fsub_rn((float)shifts_raw[b * NUM_SEG + g], 16.0f));
        float rr = rintf(st);                     // round-half-even == jnp.round
        rr = fminf(fmaxf(rr, 0.0f), 3072.0f);
        s_start[g] = (int)rr;
        s_coef[g]  = __fmul_rn(s_amp, fmaxf(seg_scale[g], 0.0f));
    }
    __syncthreads();

    // ---------- apply (float4) ----------
    {
        const float4* x4 = (const float4*)xr;
        float4* o4 = (float4*)(out + (size_t)b * 2 * LEN);
        const int   st0 = s_start[0], st1 = s_start[1], st2 = s_start[2], st3 = s_start[3];
        const float cf0 = s_coef[0],  cf1 = s_coef[1],  cf2 = s_coef[2],  cf3 = s_coef[3];

        #pragma unroll
        for (int v = tid; v < 1024; v += 512) {
            int l = 4 * v;
            float4 xa = x4[v];
            float4 xb = x4[1024 + v];
            float a[4] = {0.f, 0.f, 0.f, 0.f};
            float c[4] = {0.f, 0.f, 0.f, 0.f};
            #pragma unroll
            for (int j = 0; j < 4; j++) {
                int o;
                o = l + j - st0; if ((unsigned)o < (unsigned)SEG_LEN) { a[j] += cf0 * g_pat[0][o]; c[j] += cf0 * g_pat[1][o]; }
                o = l + j - st1; if ((unsigned)o < (unsigned)SEG_LEN) { a[j] += cf1 * g_pat[0][o]; c[j] += cf1 * g_pat[1][o]; }
                o = l + j - st2; if ((unsigned)o < (unsigned)SEG_LEN) { a[j] += cf2 * g_pat[0][o]; c[j] += cf2 * g_pat[1][o]; }
                o = l + j - st3; if ((unsigned)o < (unsigned)SEG_LEN) { a[j] += cf3 * g_pat[0][o]; c[j] += cf3 * g_pat[1][o]; }
            }
            float4 oa, ob;
            oa.x = xa.x + a[0]; oa.y = xa.y + a[1]; oa.z = xa.z + a[2]; oa.w = xa.w + a[3];
            ob.x = xb.x + c[0]; ob.y = xb.y + c[1]; ob.z = xb.z + c[2]; ob.w = xb.w + c[3];
            o4[v] = oa;
            o4[1024 + v] = ob;
        }
    }
}

extern "C" void kernel_launch(void* const* d_in, const int* in_sizes, int n_in,
                              void* d_out, int out_size) {
    const float* x          = (const float*)d_in[0];
    const float* pattern_i  = (const float*)d_in[1];
    const float* pattern_q  = (const float*)d_in[2];
    const float* seg_scale  = (const float*)d_in[3];
    const int*   rand_cols  = (const int*)d_in[4];
    const int*   shifts_raw = (const int*)d_in[5];
    float*       out        = (float*)d_out;

    k_init<<<4, 512>>>(pattern_i, pattern_q);
    k_main<<<BATCH, 512>>>(x, seg_scale, rand_cols, shifts_raw, out);
}

// round 13
// speedup vs baseline: 1.8572x; 1.3061x over previous
#include <cuda_runtime.h>
#include <stdint.h>
#include <math.h>

#define BATCH   4096
#define LEN     4096
#define NUM_SEG 4
#define SEG_LEN 1024
#define NV      3073        // LEN - SEG_LEN + 1
#define PADN    5120        // LEN + 2*512
#define NT1     320         // 5120 / 16
#define NT2     20          // 320 / 16
#define MCAP    64

// tanh pattern tables (precomputed once)
__device__ float g_pat[2][SEG_LEN];

__global__ void k_init(const float* __restrict__ pi, const float* __restrict__ pq) {
    int t = blockIdx.x * blockDim.x + threadIdx.x;
    if (t < SEG_LEN) {
        g_pat[0][t] = tanhf(pi[t]);
        g_pat[1][t] = tanhf(pq[t]);
    }
}

// warp-aggregated histogram increment (pass A only: near-total same-bin traffic)
__device__ __forceinline__ void hist_add(unsigned int* h, unsigned int bin, bool cond) {
    unsigned int active = __ballot_sync(0xFFFFFFFFu, cond);
    if (cond) {
        unsigned int mm = __match_any_sync(active, bin);
        unsigned int leader = __ffs(mm) - 1u;
        if ((threadIdx.x & 31u) == leader)
            atomicAdd(&h[bin], (unsigned int)__popc(mm));
    }
}

__global__ void __launch_bounds__(512, 4)
k_main(const float* __restrict__ x,
       const float* __restrict__ seg_scale,
       const int*   __restrict__ rand_cols,
       const int*   __restrict__ shifts_raw,
       float*       __restrict__ out) {
    __shared__ __align__(16) float BUF[PADN];   // power -> inner1 -> C
    __shared__ unsigned int US[NV];             // valid[l] bit patterns
    __shared__ unsigned int H1[1024];           // pass-A 10-bit hist, then pass-C 4x256 hists
    __shared__ unsigned int H2[NUM_SEG][256];   // pass-B per-group histograms
    __shared__ unsigned int spart[512];         // decide partials (A uses 128, B/C use 512)
    __shared__ float        sA[NT1];
    __shared__ float        sB[32];
    __shared__ float        sExcl3;
    __shared__ int          mlist[NUM_SEG][MCAP];
    __shared__ int          mcnt[NUM_SEG];
    __shared__ unsigned int sel_prefix[NUM_SEG];
    __shared__ int          sel_rank[NUM_SEG];
    __shared__ int          s_start[NUM_SEG];
    __shared__ float        s_coef[NUM_SEG];
    __shared__ float        s_amp;

    const int b   = blockIdx.x;
    const int tid = threadIdx.x;
    const float* xr = x + (size_t)b * 2 * LEN;

    // ---------- phase 1: padded power (float4) + init ----------
    // power[j] = rn(rn(x0*x0) + rn(x1*x1)) — XLA reduce emitter, no contraction
    {
        const float4* x4 = (const float4*)xr;
        #pragma unroll
        for (int v = tid; v < 1024; v += 512) {
            float4 a = x4[v];
            float4 c = x4[1024 + v];
            int o = 512 + 4 * v;
            BUF[o + 0] = __fadd_rn(__fmul_rn(a.x, a.x), __fmul_rn(c.x, c.x));
            BUF[o + 1] = __fadd_rn(__fmul_rn(a.y, a.y), __fmul_rn(c.y, c.y));
            BUF[o + 2] = __fadd_rn(__fmul_rn(a.z, a.z), __fmul_rn(c.z, c.z));
            BUF[o + 3] = __fadd_rn(__fmul_rn(a.w, a.w), __fmul_rn(c.w, c.w));
        }
        BUF[tid] = 0.0f;           // pad [0,512)
        BUF[4608 + tid] = 0.0f;    // pad [4608,5120)
        H1[tid] = 0u; H1[512 + tid] = 0u;
        ((unsigned int*)H2)[tid] = 0u; ((unsigned int*)H2)[512 + tid] = 0u;
        if (tid < NUM_SEG) {
            sel_rank[tid]   = rand_cols[b * NUM_SEG + tid];
            sel_prefix[tid] = 0u;
            mcnt[tid]       = 0;
        }
    }
    __syncthreads();

    // ---------- phase 2: XLA ReduceWindowRewriter blocked scan (base 16) ----------
    if (tid < NT1) {
        float4* t4 = (float4*)(BUF + 16 * tid);
        float4 v0 = t4[0], v1 = t4[1], v2 = t4[2], v3 = t4[3];
        float s;
        s = v0.x;
        s = __fadd_rn(s, v0.y); v0.y = s;
        s = __fadd_rn(s, v0.z); v0.z = s;
        s = __fadd_rn(s, v0.w); v0.w = s;
        s = __fadd_rn(s, v1.x); v1.x = s;
        s = __fadd_rn(s, v1.y); v1.y = s;
        s = __fadd_rn(s, v1.z); v1.z = s;
        s = __fadd_rn(s, v1.w); v1.w = s;
        s = __fadd_rn(s, v2.x); v2.x = s;
        s = __fadd_rn(s, v2.y); v2.y = s;
        s = __fadd_rn(s, v2.z); v2.z = s;
        s = __fadd_rn(s, v2.w); v2.w = s;
        s = __fadd_rn(s, v3.x); v3.x = s;
        s = __fadd_rn(s, v3.y); v3.y = s;
        s = __fadd_rn(s, v3.z); v3.z = s;
        s = __fadd_rn(s, v3.w); v3.w = s;
        t4[0] = v0; t4[1] = v1; t4[2] = v2; t4[3] = v3;
        sA[tid] = s;
    }
    __syncthreads();

    if (tid < NT2) {
        float acc = sA[16 * tid];
        #pragma unroll
        for (int r = 1; r < 16; r++) {
            acc = __fadd_rn(acc, sA[16 * tid + r]);
            sA[16 * tid + r] = acc;
        }
        sB[tid] = acc;
    }
    if (tid >= NT2 && tid < 32) sB[tid] = 0.0f;
    __syncthreads();

    if (tid < 2) {
        float acc = sB[16 * tid];
        #pragma unroll
        for (int r = 1; r < 16; r++) {
            acc = __fadd_rn(acc, sB[16 * tid + r]);
            sB[16 * tid + r] = acc;
        }
        if (tid == 0) sExcl3 = acc;
    }
    __syncthreads();

    if (tid < NT1) {
        int q = tid >> 4;
        float excl2;
        if (q == 0) excl2 = 0.0f;
        else {
            int j = q - 1;
            float e3 = (j < 16) ? 0.0f : sExcl3;
            excl2 = __fadd_rn(sB[j], e3);
        }
        sA[tid] = __fadd_rn(sA[tid], excl2);
    }
    __syncthreads();

    if (tid < NT1) {
        float excl1 = (tid == 0) ? 0.0f : sA[tid - 1];
        float4* t4 = (float4*)(BUF + 16 * tid);
        #pragma unroll
        for (int q = 0; q < 4; q++) {
            float4 v = t4[q];
            v.x = __fadd_rn(v.x, excl1);
            v.y = __fadd_rn(v.y, excl1);
            v.z = __fadd_rn(v.z, excl1);
            v.w = __fadd_rn(v.w, excl1);
            t4[q] = v;
        }
    }
    __syncthreads();
    const float* C = BUF;

    const int g  = tid >> 7;          // group 0..3; even = desc (high pool)
    const int lt = tid & 127;

    if (tid == 256) {
        float mean = __fadd_rn(__fdiv_rn(C[512 + LEN - 1], 8192.0f), 1e-12f);
        s_amp = 0.08f * sqrtf(mean);
    }

    // ---------- pass A: fill US + 10-bit histogram (bits [31:22]) ----------
    for (int base = 0; base < NV; base += 512) {
        int l = base + tid;
        bool inb = l < NV;
        unsigned int u = 0u;
        if (inb) {
            float c1 = C[l + 1023];
            float c0 = (l > 0) ? C[l - 1] : 0.0f;
            u = __float_as_uint(__fmul_rn(__fsub_rn(c1, c0), 0.0009765625f));
            US[l] = u;
        }
        hist_add(H1, u >> 22, inb);
    }
    __syncthreads();

    // decide A: 1024 bins; partials (8 bins/thread) + per-group leader walk
    if (tid < 128) {
        unsigned int s = 0u;
        #pragma unroll
        for (int j = 0; j < 8; j++) s += H1[8 * tid + j];
        spart[tid] = s;
    }
    __syncthreads();
    if (lt == 0) {
        const bool desc = (g & 1) == 0;
        int r = sel_rank[g];
        unsigned int cum = 0;
        int bin;
        if (desc) {
            int t = 127;
            for (;; t--) { if ((int)(cum + spart[t]) > r) break; cum += spart[t]; }
            bin = 8 * t + 7;
            for (;; bin--) { if ((int)(cum + H1[bin]) > r) break; cum += H1[bin]; }
        } else {
            int t = 0;
            for (;; t++) { if ((int)(cum + spart[t]) > r) break; cum += spart[t]; }
            bin = 8 * t;
            for (;; bin++) { if ((int)(cum + H1[bin]) > r) break; cum += H1[bin]; }
        }
        sel_prefix[g] = (unsigned int)bin;      // 10-bit prefix
        sel_rank[g]   = r - (int)cum;
    }
    __syncthreads();

    // ---------- pass B: bits [21:14], per-group, plain predicated atomics ----------
    // (also re-zero H1 for reuse as pass-C histograms — decide A is complete)
    {
        H1[tid] = 0u; H1[512 + tid] = 0u;
        const unsigned int p0 = sel_prefix[0], p1 = sel_prefix[1],
                           p2 = sel_prefix[2], p3 = sel_prefix[3];
        for (int base = 0; base < NV; base += 512) {
            int l = base + tid;
            if (l >= NV) continue;
            unsigned int u = US[l];
            unsigned int hi = u >> 22;
            unsigned int bin = (u >> 14) & 255u;
            if (hi == p0) atomicAdd(&H2[0][bin], 1u);
            if (hi == p1) atomicAdd(&H2[1][bin], 1u);
            if (hi == p2) atomicAdd(&H2[2][bin], 1u);
            if (hi == p3) atomicAdd(&H2[3][bin], 1u);
        }
    }
    __syncthreads();

    // decide B: 256 bins per group; partials (2 bins/thread) + leader walk
    spart[tid] = H2[g][2 * lt] + H2[g][2 * lt + 1];
    __syncthreads();
    if (lt == 0) {
        const bool desc = (g & 1) == 0;
        const unsigned int* part = spart + (g << 7);
        int r = sel_rank[g];
        unsigned int cum = 0;
        int bin;
        if (desc) {
            int t = 127;
            for (;; t--) { if ((int)(cum + part[t]) > r) break; cum += part[t]; }
            bin = 2 * t + 1;
            for (;; bin--) { if ((int)(cum + H2[g][bin]) > r) break; cum += H2[g][bin]; }
        } else {
            int t = 0;
            for (;; t++) { if ((int)(cum + part[t]) > r) break; cum += part[t]; }
            bin = 2 * t;
            for (;; bin++) { if ((int)(cum + H2[g][bin]) > r) break; cum += H2[g][bin]; }
        }
        sel_prefix[g] = (sel_prefix[g] << 8) | (unsigned int)bin;   // 18-bit prefix
        sel_rank[g]   = r - (int)cum;
    }
    __syncthreads();

    // ---------- pass C: bits [13:6], per-group, hists in H1 (4x256) ----------
    {
        const unsigned int q0 = sel_prefix[0], q1 = sel_prefix[1],
                           q2 = sel_prefix[2], q3 = sel_prefix[3];
        unsigned int (*HC)[256] = (unsigned int (*)[256])H1;
        for (int base = 0; base < NV; base += 512) {
            int l = base + tid;
            if (l >= NV) continue;
            unsigned int u = US[l];
            unsigned int hi = u >> 14;
            unsigned int bin = (u >> 6) & 255u;
            if (hi == q0) atomicAdd(&HC[0][bin], 1u);
            if (hi == q1) atomicAdd(&HC[1][bin], 1u);
            if (hi == q2) atomicAdd(&HC[2][bin], 1u);
            if (hi == q3) atomicAdd(&HC[3][bin], 1u);
        }
    }
    __syncthreads();

    // decide C: 256 bins per group (hists in H1)
    {
        const unsigned int* HCg = H1 + (g << 8);
        spart[tid] = HCg[2 * lt] + HCg[2 * lt + 1];
    }
    __syncthreads();
    if (lt == 0) {
        const bool desc = (g & 1) == 0;
        const unsigned int* part = spart + (g << 7);
        const unsigned int* HCg  = H1 + (g << 8);
        int r = sel_rank[g];
        unsigned int cum = 0;
        int bin;
        if (desc) {
            int t = 127;
            for (;; t--) { if ((int)(cum + part[t]) > r) break; cum += part[t]; }
            bin = 2 * t + 1;
            for (;; bin--) { if ((int)(cum + HCg[bin]) > r) break; cum += HCg[bin]; }
        } else {
            int t = 0;
            for (;; t++) { if ((int)(cum + part[t]) > r) break; cum += part[t]; }
            bin = 2 * t;
            for (;; bin++) { if ((int)(cum + HCg[bin]) > r) break; cum += HCg[bin]; }
        }
        sel_prefix[g] = (sel_prefix[g] << 8) | (unsigned int)bin;   // 26-bit prefix
        sel_rank[g]   = r - (int)cum;
    }
    __syncthreads();

    // ---------- compact: values matching each group's 26-bit prefix ----------
    {
        const unsigned int q0 = sel_prefix[0], q1 = sel_prefix[1],
                           q2 = sel_prefix[2], q3 = sel_prefix[3];
        for (int base = 0; base < NV; base += 512) {
            int l = base + tid;
            if (l >= NV) continue;
            unsigned int hi = US[l] >> 6;
            if (hi == q0) { int p = atomicAdd(&mcnt[0], 1); if (p < MCAP) mlist[0][p] = l; }
            if (hi == q1) { int p = atomicAdd(&mcnt[1], 1); if (p < MCAP) mlist[1][p] = l; }
            if (hi == q2) { int p = atomicAdd(&mcnt[2], 1); if (p < MCAP) mlist[2][p] = l; }
            if (hi == q3) { int p = atomicAdd(&mcnt[3], 1); if (p < MCAP) mlist[3][p] = l; }
        }
    }
    __syncthreads();

    // final decide: r-th smallest 64-bit key (value, index); desc flips value bits
    if (lt == 0) {
        const bool desc = (g & 1) == 0;
        int n = min(mcnt[g], MCAP);
        int r = min(sel_rank[g], n - 1);
        unsigned long long cur = 0ULL;
        int idx = 0;
        for (int it = 0; it <= r; it++) {
            unsigned long long mn = 0xFFFFFFFFFFFFFFFFULL;
            int mnidx = 0;
            for (int j = 0; j < n; j++) {
                int l = mlist[g][j];
                unsigned int uv = US[l];
                unsigned int key_hi = desc ? ~uv : uv;
                unsigned long long key = ((unsigned long long)key_hi << 32) | (unsigned int)l;
                if (key > cur && key < mn) { mn = key; mnidx = l; }
            }
            cur = mn;
            idx = mnidx;
        }

        // starts: strict fp32 replication of reference op sequence
        const float a0f = 409.600006103515625f;   // fp32(0.1*4096)
        const float a3f = 3194.8798828125f;       // fp32(0.78*4096)
        float step   = __fdiv_rn(__fsub_rn(a3f, a0f), 3.0f);
        float anchor = __fadd_rn(a0f, __fmul_rn((float)g, step));
        float st = __fadd_rn(__fmul_rn(0.8f, anchor), __fmul_rn(0.2f, (float)idx));
        st = __fadd_rn(st, __fsub_rn((float)shifts_raw[b * NUM_SEG + g], 16.0f));
        float rr = rintf(st);                     // round-half-even == jnp.round
        rr = fminf(fmaxf(rr, 0.0f), 3072.0f);
        s_start[g] = (int)rr;
        s_coef[g]  = __fmul_rn(s_amp, fmaxf(seg_scale[g], 0.0f));
    }
    __syncthreads();

    // ---------- apply (float4, per-chunk segment skip) ----------
    {
        const float4* x4 = (const float4*)xr;
        float4* o4 = (float4*)(out + (size_t)b * 2 * LEN);
        const int   st0 = s_start[0], st1 = s_start[1], st2 = s_start[2], st3 = s_start[3];
        const float cf0 = s_coef[0],  cf1 = s_coef[1],  cf2 = s_coef[2],  cf3 = s_coef[3];

        #pragma unroll
        for (int v = tid; v < 1024; v += 512) {
            int l = 4 * v;
            float4 xa = x4[v];
            float4 xb = x4[1024 + v];
            float a[4] = {0.f, 0.f, 0.f, 0.f};
            float c[4] = {0.f, 0.f, 0.f, 0.f};
            int off;
            off = l - st0;
            if ((unsigned)(off + 3) <= 1026u) {
                #pragma unroll
                for (int j = 0; j < 4; j++) { int o = off + j; if ((unsigned)o < 1024u) { a[j] += cf0 * g_pat[0][o]; c[j] += cf0 * g_pat[1][o]; } }
            }
            off = l - st1;
            if ((unsigned)(off + 3) <= 1026u) {
                #pragma unroll
                for (int j = 0; j < 4; j++) { int o = off + j; if ((unsigned)o < 1024u) { a[j] += cf1 * g_pat[0][o]; c[j] += cf1 * g_pat[1][o]; } }
            }
            off = l - st2;
            if ((unsigned)(off + 3) <= 1026u) {
                #pragma unroll
                for (int j = 0; j < 4; j++) { int o = off + j; if ((unsigned)o < 1024u) { a[j] += cf2 * g_pat[0][o]; c[j] += cf2 * g_pat[1][o]; } }
            }
            off = l - st3;
            if ((unsigned)(off + 3) <= 1026u) {
                #pragma unroll
                for (int j = 0; j < 4; j++) { int o = off + j; if ((unsigned)o < 1024u) { a[j] += cf3 * g_pat[0][o]; c[j] += cf3 * g_pat[1][o]; } }
            }
            float4 oa, ob;
            oa.x = xa.x + a[0]; oa.y = xa.y + a[1]; oa.z = xa.z + a[2]; oa.w = xa.w + a[3];
            ob.x = xb.x + c[0]; ob.y = xb.y + c[1]; ob.z = xb.z + c[2]; ob.w = xb.w + c[3];
            o4[v] = oa;
            o4[1024 + v] = ob;
        }
    }
}

extern "C" void kernel_launch(void* const* d_in, const int* in_sizes, int n_in,
                              void* d_out, int out_size) {
    const float* x          = (const float*)d_in[0];
    const float* pattern_i  = (const float*)d_in[1];
    const float* pattern_q  = (const float*)d_in[2];
    const float* seg_scale  = (const float*)d_in[3];
    const int*   rand_cols  = (const int*)d_in[4];
    const int*   shifts_raw = (const int*)d_in[5];
    float*       out        = (float*)d_out;

    k_init<<<4, 512>>>(pattern_i, pattern_q);
    k_main<<<BATCH, 512>>>(x, seg_scale, rand_cols, shifts_raw, out);
}

// round 14
// speedup vs baseline: 2.7705x; 1.4918x over previous
#include <cuda_runtime.h>
#include <stdint.h>
#include <math.h>

#define BATCH   4096
#define LEN     4096
#define NUM_SEG 4
#define SEG_LEN 1024
#define NV      3073        // LEN - SEG_LEN + 1
#define PADN    5120        // LEN + 2*512
#define NT1     320         // 5120 / 16
#define NT2     20          // 320 / 16
#define NBIN    2048
#define MCAP    128

// tanh pattern tables (precomputed once)
__device__ float g_pat[2][SEG_LEN];

__global__ void k_init(const float* __restrict__ pi, const float* __restrict__ pq) {
    int t = blockIdx.x * blockDim.x + threadIdx.x;
    if (t < SEG_LEN) {
        g_pat[0][t] = tanhf(pi[t]);
        g_pat[1][t] = tanhf(pq[t]);
    }
}

__global__ void __launch_bounds__(512, 4)
k_main(const float* __restrict__ x,
       const float* __restrict__ seg_scale,
       const int*   __restrict__ rand_cols,
       const int*   __restrict__ shifts_raw,
       float*       __restrict__ out) {
    __shared__ __align__(16) float BUF[PADN];   // power -> inner1 -> C
    __shared__ unsigned int US[NV];             // valid[l] bit patterns
    __shared__ unsigned int H[NBIN];            // histogram over exact value range
    __shared__ unsigned int P1[512];            // partials: 4 bins each
    __shared__ unsigned int P2[32];             // partials: 64 bins each
    __shared__ unsigned long long klist[NUM_SEG][MCAP];
    __shared__ float        sA[NT1];
    __shared__ float        sB[32];
    __shared__ float        sExcl3;
    __shared__ int          mcnt[NUM_SEG];
    __shared__ int          sel_bin[NUM_SEG];
    __shared__ int          sel_rank[NUM_SEG];
    __shared__ unsigned int s_umin, s_umax;
    __shared__ int          s_start[NUM_SEG];
    __shared__ float        s_coef[NUM_SEG];
    __shared__ float        s_amp;

    const int b   = blockIdx.x;
    const int tid = threadIdx.x;
    const float* xr = x + (size_t)b * 2 * LEN;

    // ---------- phase 1: padded power (float4) + init ----------
    // power[j] = rn(rn(x0*x0) + rn(x1*x1)) — XLA reduce emitter, no contraction
    {
        const float4* x4 = (const float4*)xr;
        #pragma unroll
        for (int v = tid; v < 1024; v += 512) {
            float4 a = x4[v];
            float4 c = x4[1024 + v];
            int o = 512 + 4 * v;
            BUF[o + 0] = __fadd_rn(__fmul_rn(a.x, a.x), __fmul_rn(c.x, c.x));
            BUF[o + 1] = __fadd_rn(__fmul_rn(a.y, a.y), __fmul_rn(c.y, c.y));
            BUF[o + 2] = __fadd_rn(__fmul_rn(a.z, a.z), __fmul_rn(c.z, c.z));
            BUF[o + 3] = __fadd_rn(__fmul_rn(a.w, a.w), __fmul_rn(c.w, c.w));
        }
        BUF[tid] = 0.0f;           // pad [0,512)
        BUF[4608 + tid] = 0.0f;    // pad [4608,5120)
        H[tid] = 0u; H[512 + tid] = 0u; H[1024 + tid] = 0u; H[1536 + tid] = 0u;
        if (tid < NUM_SEG) {
            sel_rank[tid] = rand_cols[b * NUM_SEG + tid];
            mcnt[tid]     = 0;
        }
        if (tid == 4) { s_umin = 0xFFFFFFFFu; s_umax = 0u; }
    }
    __syncthreads();

    // ---------- phase 2: XLA ReduceWindowRewriter blocked scan (base 16) ----------
    if (tid < NT1) {
        float4* t4 = (float4*)(BUF + 16 * tid);
        float4 v0 = t4[0], v1 = t4[1], v2 = t4[2], v3 = t4[3];
        float s;
        s = v0.x;
        s = __fadd_rn(s, v0.y); v0.y = s;
        s = __fadd_rn(s, v0.z); v0.z = s;
        s = __fadd_rn(s, v0.w); v0.w = s;
        s = __fadd_rn(s, v1.x); v1.x = s;
        s = __fadd_rn(s, v1.y); v1.y = s;
        s = __fadd_rn(s, v1.z); v1.z = s;
        s = __fadd_rn(s, v1.w); v1.w = s;
        s = __fadd_rn(s, v2.x); v2.x = s;
        s = __fadd_rn(s, v2.y); v2.y = s;
        s = __fadd_rn(s, v2.z); v2.z = s;
        s = __fadd_rn(s, v2.w); v2.w = s;
        s = __fadd_rn(s, v3.x); v3.x = s;
        s = __fadd_rn(s, v3.y); v3.y = s;
        s = __fadd_rn(s, v3.z); v3.z = s;
        s = __fadd_rn(s, v3.w); v3.w = s;
        t4[0] = v0; t4[1] = v1; t4[2] = v2; t4[3] = v3;
        sA[tid] = s;
    }
    __syncthreads();

    if (tid < NT2) {
        float acc = sA[16 * tid];
        #pragma unroll
        for (int r = 1; r < 16; r++) {
            acc = __fadd_rn(acc, sA[16 * tid + r]);
            sA[16 * tid + r] = acc;
        }
        sB[tid] = acc;
    }
    if (tid >= NT2 && tid < 32) sB[tid] = 0.0f;
    __syncthreads();

    if (tid < 2) {
        float acc = sB[16 * tid];
        #pragma unroll
        for (int r = 1; r < 16; r++) {
            acc = __fadd_rn(acc, sB[16 * tid + r]);
            sB[16 * tid + r] = acc;
        }
        if (tid == 0) sExcl3 = acc;
    }
    __syncthreads();

    if (tid < NT1) {
        int q = tid >> 4;
        float excl2;
        if (q == 0) excl2 = 0.0f;
        else {
            int j = q - 1;
            float e3 = (j < 16) ? 0.0f : sExcl3;
            excl2 = __fadd_rn(sB[j], e3);
        }
        sA[tid] = __fadd_rn(sA[tid], excl2);
    }
    __syncthreads();

    if (tid < NT1) {
        float excl1 = (tid == 0) ? 0.0f : sA[tid - 1];
        float4* t4 = (float4*)(BUF + 16 * tid);
        #pragma unroll
        for (int q = 0; q < 4; q++) {
            float4 v = t4[q];
            v.x = __fadd_rn(v.x, excl1);
            v.y = __fadd_rn(v.y, excl1);
            v.z = __fadd_rn(v.z, excl1);
            v.w = __fadd_rn(v.w, excl1);
            t4[q] = v;
        }
    }
    __syncthreads();
    const float* C = BUF;

    const int g  = tid >> 7;          // group 0..3; even = desc (high pool)
    const int lt = tid & 127;

    if (tid == 256) {
        float mean = __fadd_rn(__fdiv_rn(C[512 + LEN - 1], 8192.0f), 1e-12f);
        s_amp = 0.08f * sqrtf(mean);
    }

    // ---------- pass 1: fill US + min/max ----------
    {
        unsigned int lmin = 0xFFFFFFFFu, lmax = 0u;
        for (int base = 0; base < NV; base += 512) {
            int l = base + tid;
            if (l < NV) {
                float c1 = C[l + 1023];
                float c0 = (l > 0) ? C[l - 1] : 0.0f;
                unsigned int u = __float_as_uint(__fmul_rn(__fsub_rn(c1, c0), 0.0009765625f));
                US[l] = u;
                lmin = min(lmin, u);
                lmax = max(lmax, u);
            }
        }
        lmin = __reduce_min_sync(0xFFFFFFFFu, lmin);
        lmax = __reduce_max_sync(0xFFFFFFFFu, lmax);
        if ((tid & 31) == 0) {
            atomicMin(&s_umin, lmin);
            atomicMax(&s_umax, lmax);
        }
    }
    __syncthreads();

    // ---------- pass 2: histogram over exact range ----------
    const unsigned int umin  = s_umin;
    const unsigned int range = s_umax - umin;
    const int shift = max(0, 21 - __clz(range | 1u));
    for (int base = 0; base < NV; base += 512) {
        int l = base + tid;
        if (l < NV) atomicAdd(&H[(US[l] - umin) >> shift], 1u);
    }
    __syncthreads();

    // partial sums: P1[t] = 4 bins, P2[t] = 64 bins
    P1[tid] = H[4 * tid] + H[4 * tid + 1] + H[4 * tid + 2] + H[4 * tid + 3];
    __syncthreads();
    if (tid < 32) {
        unsigned int s = 0u;
        #pragma unroll
        for (int j = 0; j < 16; j++) s += P1[16 * tid + j];
        P2[tid] = s;
    }
    __syncthreads();

    // decide: hierarchical walk (<=52 serial steps), one leader per group
    if (lt == 0) {
        const bool desc = (g & 1) == 0;
        int r = sel_rank[g];
        unsigned int cum = 0;
        int bin;
        if (desc) {
            int t2 = 31;
            for (;; t2--) { if ((int)(cum + P2[t2]) > r) break; cum += P2[t2]; }
            int t1 = 16 * t2 + 15;
            for (;; t1--) { if ((int)(cum + P1[t1]) > r) break; cum += P1[t1]; }
            bin = 4 * t1 + 3;
            for (;; bin--) { if ((int)(cum + H[bin]) > r) break; cum += H[bin]; }
        } else {
            int t2 = 0;
            for (;; t2++) { if ((int)(cum + P2[t2]) > r) break; cum += P2[t2]; }
            int t1 = 16 * t2;
            for (;; t1++) { if ((int)(cum + P1[t1]) > r) break; cum += P1[t1]; }
            bin = 4 * t1;
            for (;; bin++) { if ((int)(cum + H[bin]) > r) break; cum += H[bin]; }
        }
        sel_bin[g]  = bin;
        sel_rank[g] = r - (int)cum;
    }
    __syncthreads();

    // ---------- pass 3: compact candidate keys per group ----------
    {
        const int b0 = sel_bin[0], b1 = sel_bin[1], b2 = sel_bin[2], b3 = sel_bin[3];
        for (int base = 0; base < NV; base += 512) {
            int l = base + tid;
            if (l >= NV) continue;
            unsigned int u = US[l];
            int bin = (int)((u - umin) >> shift);
            if (bin == b0) { int p = atomicAdd(&mcnt[0], 1); if (p < MCAP) klist[0][p] = ((unsigned long long)(~u) << 32) | (unsigned int)l; }
            if (bin == b1) { int p = atomicAdd(&mcnt[1], 1); if (p < MCAP) klist[1][p] = ((unsigned long long)( u) << 32) | (unsigned int)l; }
            if (bin == b2) { int p = atomicAdd(&mcnt[2], 1); if (p < MCAP) klist[2][p] = ((unsigned long long)(~u) << 32) | (unsigned int)l; }
            if (bin == b3) { int p = atomicAdd(&mcnt[3], 1); if (p < MCAP) klist[3][p] = ((unsigned long long)( u) << 32) | (unsigned int)l; }
        }
    }
    __syncthreads();

    // final: warp-parallel rank count; keys distinct => unique rank-r match
    if (lt < 32) {
        int n = min(mcnt[g], MCAP);
        int r = min(sel_rank[g], n - 1);
        for (int j = lt; j < n; j += 32) {
            unsigned long long kj = klist[g][j];
            int rk = 0;
            for (int k = 0; k < n; k++) rk += (klist[g][k] < kj) ? 1 : 0;
            if (rk == r) {
                int idx = (int)(kj & 0xFFFFFFFFu);
                // starts: strict fp32 replication of reference op sequence
                const float a0f = 409.600006103515625f;   // fp32(0.1*4096)
                const float a3f = 3194.8798828125f;       // fp32(0.78*4096)
                float step   = __fdiv_rn(__fsub_rn(a3f, a0f), 3.0f);
                float anchor = __fadd_rn(a0f, __fmul_rn((float)g, step));
                float st = __fadd_rn(__fmul_rn(0.8f, anchor), __fmul_rn(0.2f, (float)idx));
                st = __fadd_rn(st, __fsub_rn((float)shifts_raw[b * NUM_SEG + g], 16.0f));
                float rr = rintf(st);                     // round-half-even == jnp.round
                rr = fminf(fmaxf(rr, 0.0f), 3072.0f);
                s_start[g] = (int)rr;
                s_coef[g]  = __fmul_rn(s_amp, fmaxf(seg_scale[g], 0.0f));
            }
        }
    }
    __syncthreads();

    // ---------- apply (float4, per-chunk segment skip) ----------
    {
        const float4* x4 = (const float4*)xr;
        float4* o4 = (float4*)(out + (size_t)b * 2 * LEN);
        const int   st0 = s_start[0], st1 = s_start[1], st2 = s_start[2], st3 = s_start[3];
        const float cf0 = s_coef[0],  cf1 = s_coef[1],  cf2 = s_coef[2],  cf3 = s_coef[3];

        #pragma unroll
        for (int v = tid; v < 1024; v += 512) {
            int l = 4 * v;
            float4 xa = x4[v];
            float4 xb = x4[1024 + v];
            float a[4] = {0.f, 0.f, 0.f, 0.f};
            float c[4] = {0.f, 0.f, 0.f, 0.f};
            int off;
            off = l - st0;
            if ((unsigned)(off + 3) <= 1026u) {
                #pragma unroll
                for (int j = 0; j < 4; j++) { int o = off + j; if ((unsigned)o < 1024u) { a[j] += cf0 * g_pat[0][o]; c[j] += cf0 * g_pat[1][o]; } }
            }
            off = l - st1;
            if ((unsigned)(off + 3) <= 1026u) {
                #pragma unroll
                for (int j = 0; j < 4; j++) { int o = off + j; if ((unsigned)o < 1024u) { a[j] += cf1 * g_pat[0][o]; c[j] += cf1 * g_pat[1][o]; } }
            }
            off = l - st2;
            if ((unsigned)(off + 3) <= 1026u) {
                #pragma unroll
                for (int j = 0; j < 4; j++) { int o = off + j; if ((unsigned)o < 1024u) { a[j] += cf2 * g_pat[0][o]; c[j] += cf2 * g_pat[1][o]; } }
            }
            off = l - st3;
            if ((unsigned)(off + 3) <= 1026u) {
                #pragma unroll
                for (int j = 0; j < 4; j++) { int o = off + j; if ((unsigned)o < 1024u) { a[j] += cf3 * g_pat[0][o]; c[j] += cf3 * g_pat[1][o]; } }
            }
            float4 oa, ob;
            oa.x = xa.x + a[0]; oa.y = xa.y + a[1]; oa.z = xa.z + a[2]; oa.w = xa.w + a[3];
            ob.x = xb.x + c[0]; ob.y = xb.y + c[1]; ob.z = xb.z + c[2]; ob.w = xb.w + c[3];
            o4[v] = oa;
            o4[1024 + v] = ob;
        }
    }
}

extern "C" void kernel_launch(void* const* d_in, const int* in_sizes, int n_in,
                              void* d_out, int out_size) {
    const float* x          = (const float*)d_in[0];
    const float* pattern_i  = (const float*)d_in[1];
    const float* pattern_q  = (const float*)d_in[2];
    const float* seg_scale  = (const float*)d_in[3];
    const int*   rand_cols  = (const int*)d_in[4];
    const int*   shifts_raw = (const int*)d_in[5];
    float*       out        = (float*)d_out;

    k_init<<<4, 512>>>(pattern_i, pattern_q);
    k_main<<<BATCH, 512>>>(x, seg_scale, rand_cols, shifts_raw, out);
}